// round 2
// baseline (speedup 1.0000x reference)
#include <cuda_runtime.h>
#include <cuda_fp16.h>
#include <cstdint>

// ============================================================================
// x[32,256,56,56] -> shift2d -> 1x1 conv W[256,256] -> BN -> ReLU
// GEMM: M = 100352 pixels, N = 256, K = 256.
// compute_103 baseline path: classic mma.sync m16n8k16 fp16, fp32 accum.
// Precision: A split into fp16 hi+lo (2 passes), W*inv rounded to fp16 once.
// ============================================================================
#define CIN    256
#define COUT   256
#define HH     56
#define WWD    56
#define HWSZ   3136
#define NPIX   100352          // 32*3136
#define CTA_M  64
#define GRID   (NPIX / CTA_M)  // 1568
#define KCH    64              // K chunk
#define NCHUNK 4

// SMEM layout (bytes):
//   [0,1024)        bias[256] f32
//   [1024, +36864)  A[buf][part][64 rows][144B]   (row stride 36 words, conflict-free)
//   [37888, +73728) B[buf][256 rows][144B]
#define OFF_A      1024
#define OFF_B      37888
#define A_BUF_STR  (2 * 64 * 36)     // words per A buffer (2 parts)
#define SMEM_BYTES 111616

// scratch (device globals are the sanctioned scratch mechanism)
__device__ __half g_w[COUT * CIN];     // W[o][c] * inv[o], fp16, k-contiguous
__device__ float  g_bias[COUT];

#define DEVINL __device__ __forceinline__

DEVINL uint32_t smem_u32(const void* p) {
    uint32_t a;
    asm("{ .reg .u64 t; cvta.to.shared.u64 t, %1; cvt.u32.u64 %0, t; }"
        : "=r"(a) : "l"(p));
    return a;
}

#define CP_ASYNC16(dst_u32, src_ptr) \
    asm volatile("cp.async.cg.shared.global [%0], [%1], 16;" \
        :: "r"(dst_u32), "l"(src_ptr) : "memory")
#define CP_COMMIT() asm volatile("cp.async.commit_group;" ::: "memory")
#define CP_WAIT0()  asm volatile("cp.async.wait_group 0;"  ::: "memory")

#define MMA16816(d, a0, a1, a2, a3, b0, b1) \
    asm volatile("mma.sync.aligned.m16n8k16.row.col.f32.f16.f16.f32 " \
        "{%0,%1,%2,%3}, {%4,%5,%6,%7}, {%8,%9}, {%0,%1,%2,%3};" \
        : "+f"((d)[0]), "+f"((d)[1]), "+f"((d)[2]), "+f"((d)[3]) \
        : "r"(a0), "r"(a1), "r"(a2), "r"(a3), "r"(b0), "r"(b1))

// channel -> shift direction index (group starts: 0,51,102,153,204)
DEVINL int ch_dir(int c) {
    return (c >= 204) ? 4 : (c >= 153) ? 3 : (c >= 102) ? 2 : (c >= 51) ? 1 : 0;
}

// ============================================================================
// prep: fold BN scale into W, convert to fp16; compute bias.
// ============================================================================
__global__ void prep_kernel(const float* __restrict__ pw,
                            const float* __restrict__ gamma,
                            const float* __restrict__ beta,
                            const float* __restrict__ rmean,
                            const float* __restrict__ rvar)
{
    const int o = blockIdx.x;
    const int c = threadIdx.x;
    const float inv_o = gamma[o] * rsqrtf(rvar[o] + 1e-5f);
    g_w[o * CIN + c] = __float2half_rn(pw[o * CIN + c] * inv_o);
    if (o == 0) {
        const float inv_c = gamma[c] * rsqrtf(rvar[c] + 1e-5f);
        g_bias[c] = beta[c] - rmean[c] * inv_c;
    }
}

// ============================================================================
// main kernel: 256 threads, warp grid 2(M) x 4(N); warp tile 32 x 64.
// ============================================================================
__global__ void __launch_bounds__(256, 1)
shiftconv_kernel(const float* __restrict__ x, float* __restrict__ out)
{
    extern __shared__ char smem[];
    float*    sbias = (float*)smem;
    uint32_t* sA    = (uint32_t*)(smem + OFF_A);
    uint32_t* sB    = (uint32_t*)(smem + OFF_B);

    const int tid  = threadIdx.x;
    const int warp = tid >> 5;
    const int lane = tid & 31;
    const int gr   = lane >> 2;      // fragment "group" row
    const int lq   = lane & 3;       // fragment quad col

    const int warp_px = (warp & 1) * 32;   // M offset within CTA
    const int warp_n  = (warp >> 1) * 64;  // N offset

    sbias[tid] = g_bias[tid];

    // ---- staging thread mapping (A path) -----------------------------------
    const int pxl = tid & 63;         // pixel within CTA tile
    const int c2  = tid >> 6;         // 0..3 channel-pair lane group
    const int P   = blockIdx.x * CTA_M + pxl;
    const int bb  = P / HWSZ;
    const int rr  = P - bb * HWSZ;
    const int hh  = rr / WWD;
    const int ww  = rr - hh * WWD;
    const float* xb = x + (size_t)bb * CIN * HWSZ;

    // per-direction offsets + validity for this pixel
    // dirs (dx,dy): 0:(0,0) 1:(1,0) 2:(-1,0) 3:(0,1) 4:(0,-1); src = (h-dy, w-dx)
    int  offs[5];
    bool vald[5];
    {
        const int dxs[5] = {0, 1, -1, 0, 0};
        const int dys[5] = {0, 0, 0, 1, -1};
        #pragma unroll
        for (int d = 0; d < 5; ++d) {
            int hs = hh - dys[d], ws = ww - dxs[d];
            vald[d] = ((unsigned)hs < HH) && ((unsigned)ws < WWD);
            offs[d] = hs * WWD + ws;
        }
    }

    // B staging mapping
    const int bu = tid & 7;           // 16B unit within 128B row chunk
    const int bn = tid >> 3;          // row base (32 rows/pass)

    const uint32_t sB_u32 = smem_u32(sB);

    float vstage[16];   // staged A values (8 channel-pairs)

    // ---- helpers as lambdas -------------------------------------------------
    auto ldg_A = [&](int chunk) {
        const int c0 = chunk * KCH;
        #pragma unroll
        for (int it = 0; it < 8; ++it) {
            const int pi  = c2 * 8 + it;
            const int ch0 = c0 + 2 * pi;
            const int d0  = ch_dir(ch0);
            const int d1  = ch_dir(ch0 + 1);
            vstage[2*it]   = vald[d0] ? __ldg(xb + (size_t)ch0       * HWSZ + offs[d0]) : 0.0f;
            vstage[2*it+1] = vald[d1] ? __ldg(xb + (size_t)(ch0 + 1) * HWSZ + offs[d1]) : 0.0f;
        }
    };

    auto sts_A = [&](int buf) {
        uint32_t* Ahi = sA + buf * A_BUF_STR;
        uint32_t* Alo = Ahi + 64 * 36;
        #pragma unroll
        for (int it = 0; it < 8; ++it) {
            const int pi = c2 * 8 + it;
            float v0 = vstage[2*it], v1 = vstage[2*it+1];
            __half h0 = __float2half_rn(v0), h1 = __float2half_rn(v1);
            float  r0 = v0 - __half2float(h0), r1 = v1 - __half2float(h1);
            __half l0 = __float2half_rn(r0), l1 = __float2half_rn(r1);
            uint32_t hi = (uint32_t)__half_as_ushort(h0) | ((uint32_t)__half_as_ushort(h1) << 16);
            uint32_t lo = (uint32_t)__half_as_ushort(l0) | ((uint32_t)__half_as_ushort(l1) << 16);
            Ahi[pxl * 36 + pi] = hi;
            Alo[pxl * 36 + pi] = lo;
        }
    };

    auto cp_B = [&](int chunk, int buf) {
        const int c0 = chunk * KCH;
        #pragma unroll
        for (int itn = 0; itn < 8; ++itn) {
            const int n = bn + 32 * itn;
            const uint32_t dst = sB_u32 + (uint32_t)(buf * 256 + n) * 144 + bu * 16;
            const __half* src = g_w + (size_t)n * CIN + c0 + bu * 8;
            CP_ASYNC16(dst, src);
        }
    };

    // accumulators
    float d[2][8][4];
    #pragma unroll
    for (int mi = 0; mi < 2; ++mi)
        #pragma unroll
        for (int f = 0; f < 8; ++f)
            #pragma unroll
            for (int e = 0; e < 4; ++e) d[mi][f][e] = 0.0f;

    // ---- prologue: stage chunk 0 -------------------------------------------
    ldg_A(0);
    cp_B(0, 0);
    CP_COMMIT();
    sts_A(0);

    // ---- main loop ----------------------------------------------------------
    #pragma unroll 1
    for (int i = 0; i < NCHUNK; ++i) {
        const int buf = i & 1;
        CP_WAIT0();
        __syncthreads();                       // A(i), B(i) visible

        if (i < NCHUNK - 1) {
            ldg_A(i + 1);                      // issue global loads early
            cp_B(i + 1, buf ^ 1);
            CP_COMMIT();
        }

        // ---- compute chunk i ----
        {
            const uint32_t* Abase = sA + buf * A_BUF_STR;      // part0 (hi)
            const uint32_t* Bbase = sB + buf * 256 * 36;
            #pragma unroll
            for (int kk = 0; kk < 4; ++kk) {
                uint32_t b0[8], b1[8];
                #pragma unroll
                for (int f = 0; f < 8; ++f) {
                    const int n = warp_n + f * 8 + gr;
                    b0[f] = Bbase[n * 36 + kk * 8 + lq];
                    b1[f] = Bbase[n * 36 + kk * 8 + lq + 4];
                }
                #pragma unroll
                for (int part = 0; part < 2; ++part) {
                    const uint32_t* Ap = Abase + part * 64 * 36;
                    uint32_t a[2][4];
                    #pragma unroll
                    for (int mi = 0; mi < 2; ++mi) {
                        const int r = warp_px + mi * 16;
                        a[mi][0] = Ap[(r + gr)     * 36 + kk * 8 + lq];
                        a[mi][1] = Ap[(r + gr + 8) * 36 + kk * 8 + lq];
                        a[mi][2] = Ap[(r + gr)     * 36 + kk * 8 + lq + 4];
                        a[mi][3] = Ap[(r + gr + 8) * 36 + kk * 8 + lq + 4];
                    }
                    #pragma unroll
                    for (int mi = 0; mi < 2; ++mi)
                        #pragma unroll
                        for (int f = 0; f < 8; ++f)
                            MMA16816(d[mi][f], a[mi][0], a[mi][1], a[mi][2], a[mi][3],
                                     b0[f], b1[f]);
                }
            }
        }

        if (i < NCHUNK - 1) sts_A(buf ^ 1);    // next-iter barrier publishes it
    }

    // ---- epilogue: bias + relu + store -------------------------------------
    #pragma unroll
    for (int mi = 0; mi < 2; ++mi) {
        #pragma unroll
        for (int h2 = 0; h2 < 2; ++h2) {
            const int pxe = warp_px + mi * 16 + gr + 8 * h2;
            const int Pe  = blockIdx.x * CTA_M + pxe;
            const int be  = Pe / HWSZ;
            const int hwe = Pe - be * HWSZ;
            float* ob = out + (size_t)be * COUT * HWSZ + hwe;
            #pragma unroll
            for (int f = 0; f < 8; ++f) {
                const int o = warp_n + f * 8 + lq * 2;
                const float2 bi = *(const float2*)&sbias[o];
                float v0 = d[mi][f][h2 * 2 + 0] + bi.x;
                float v1 = d[mi][f][h2 * 2 + 1] + bi.y;
                ob[(size_t)o       * HWSZ] = fmaxf(v0, 0.0f);
                ob[(size_t)(o + 1) * HWSZ] = fmaxf(v1, 0.0f);
            }
        }
    }
}

// ============================================================================
extern "C" void kernel_launch(void* const* d_in, const int* in_sizes, int n_in,
                              void* d_out, int out_size) {
    const float* x     = (const float*)d_in[0];
    const float* pw    = (const float*)d_in[1];
    const float* gamma = (const float*)d_in[2];
    const float* beta  = (const float*)d_in[3];
    const float* rmean = (const float*)d_in[4];
    const float* rvar  = (const float*)d_in[5];
    float* out = (float*)d_out;

    static bool attr_set = false;
    if (!attr_set) {
        cudaFuncSetAttribute(shiftconv_kernel,
                             cudaFuncAttributeMaxDynamicSharedMemorySize, SMEM_BYTES);
        attr_set = true;
    }

    prep_kernel<<<COUT, CIN>>>(pw, gamma, beta, rmean, rvar);
    shiftconv_kernel<<<GRID, 256, SMEM_BYTES>>>(x, out);
}

// round 4
// speedup vs baseline: 1.2396x; 1.2396x over previous
#include <cuda_runtime.h>
#include <cuda_fp16.h>
#include <cstdint>

// ============================================================================
// x[32,256,56,56] -> shift2d -> 1x1 conv W[256,256] -> BN -> ReLU
// GEMM: M = 100352 pixels, N = 256, K = 256.
// compute_103 baseline path: mma.sync.m16n8k16 fp16 / fp32 accum.
// Single-pass fp16 (A and W both rounded once; BN scale folded into W).
// 256 threads, 2 CTAs/SM (regs capped 128, smem 93 KB).
// ============================================================================
#define CIN    256
#define COUT   256
#define HH     56
#define WWD    56
#define HWSZ   3136
#define NPIX   100352          // 32*3136
#define CTA_M  64
#define GRID   (NPIX / CTA_M)  // 1568
#define KCH    64
#define NCHUNK 4

// SMEM layout (bytes):
//   [0,1024)         bias[256] f32
//   [1024, +18432)   A[buf][64 rows][144B]  (row stride 36 words, conflict-free)
//   [19456, +73728)  B[buf][256 rows][144B]
#define OFF_A      1024
#define OFF_B      19456
#define A_BUF_W    (64 * 36)          // words per A buffer
#define SMEM_BYTES 93184

// device-global scratch (sanctioned)
__device__ __half g_w[COUT * CIN];    // W[o][c] * inv[o], fp16, k-contiguous
__device__ float  g_bias[COUT];

#define DEVINL __device__ __forceinline__

DEVINL uint32_t smem_u32(const void* p) {
    uint32_t a;
    asm("{ .reg .u64 t; cvta.to.shared.u64 t, %1; cvt.u32.u64 %0, t; }"
        : "=r"(a) : "l"(p));
    return a;
}

#define CP_ASYNC16(dst_u32, src_ptr) \
    asm volatile("cp.async.cg.shared.global [%0], [%1], 16;" \
        :: "r"(dst_u32), "l"(src_ptr) : "memory")
#define CP_COMMIT() asm volatile("cp.async.commit_group;" ::: "memory")
#define CP_WAIT0()  asm volatile("cp.async.wait_group 0;"  ::: "memory")

#define MMA16816(d, a0, a1, a2, a3, b0, b1) \
    asm volatile("mma.sync.aligned.m16n8k16.row.col.f32.f16.f16.f32 " \
        "{%0,%1,%2,%3}, {%4,%5,%6,%7}, {%8,%9}, {%0,%1,%2,%3};" \
        : "+f"((d)[0]), "+f"((d)[1]), "+f"((d)[2]), "+f"((d)[3]) \
        : "r"(a0), "r"(a1), "r"(a2), "r"(a3), "r"(b0), "r"(b1))

// channel -> shift direction index (group starts: 0,51,102,153,204)
DEVINL int ch_dir(int c) {
    return (c >= 204) ? 4 : (c >= 153) ? 3 : (c >= 102) ? 2 : (c >= 51) ? 1 : 0;
}

// ============================================================================
// prep: fold BN scale into W, convert to fp16; compute bias. 256 blk x 64 thr.
// ============================================================================
__global__ void prep_kernel(const float* __restrict__ pw,
                            const float* __restrict__ gamma,
                            const float* __restrict__ beta,
                            const float* __restrict__ rmean,
                            const float* __restrict__ rvar)
{
    const int o  = blockIdx.x;
    const int c4 = threadIdx.x;            // 0..63, handles 4 channels
    const float inv_o = gamma[o] * rsqrtf(rvar[o] + 1e-5f);
    float4 v = *reinterpret_cast<const float4*>(pw + (size_t)o * CIN + c4 * 4);
    __half2 h01 = __floats2half2_rn(v.x * inv_o, v.y * inv_o);
    __half2 h23 = __floats2half2_rn(v.z * inv_o, v.w * inv_o);
    *reinterpret_cast<__half2*>(g_w + (size_t)o * CIN + c4 * 4)     = h01;
    *reinterpret_cast<__half2*>(g_w + (size_t)o * CIN + c4 * 4 + 2) = h23;
    if (o == 0) {
        #pragma unroll
        for (int j = 0; j < 4; ++j) {
            int c = c4 * 4 + j;
            float inv_c = gamma[c] * rsqrtf(rvar[c] + 1e-5f);
            g_bias[c] = beta[c] - rmean[c] * inv_c;
        }
    }
}

// ============================================================================
// main kernel: 256 threads, warp grid 2(M) x 4(N); warp tile 32 x 64.
// ============================================================================
__global__ void __launch_bounds__(256, 2)
shiftconv_kernel(const float* __restrict__ x, float* __restrict__ out)
{
    extern __shared__ char smem[];
    float*    sbias = (float*)smem;
    uint32_t* sA    = (uint32_t*)(smem + OFF_A);
    uint32_t* sB    = (uint32_t*)(smem + OFF_B);

    const int tid  = threadIdx.x;
    const int warp = tid >> 5;
    const int lane = tid & 31;
    const int gr   = lane >> 2;      // fragment group row
    const int lq   = lane & 3;       // fragment quad col

    const int warp_px = (warp & 1) * 32;   // M offset within CTA
    const int warp_n  = (warp >> 1) * 64;  // N offset

    sbias[tid] = g_bias[tid];

    // ---- A staging thread mapping ------------------------------------------
    const int pxl = tid & 63;         // pixel within CTA tile
    const int c2  = tid >> 6;         // 0..3 channel-pair lane group
    const int P   = blockIdx.x * CTA_M + pxl;
    const int bb  = P / HWSZ;
    const int rr  = P - bb * HWSZ;
    const int hh  = rr / WWD;
    const int ww  = rr - hh * WWD;
    const float* xb = x + (size_t)bb * CIN * HWSZ;

    // dirs (dx,dy): 0:(0,0) 1:(1,0) 2:(-1,0) 3:(0,1) 4:(0,-1); src = (h-dy, w-dx)
    int  offs[5];
    bool vald[5];
    {
        const int dxs[5] = {0, 1, -1, 0, 0};
        const int dys[5] = {0, 0, 0, 1, -1};
        #pragma unroll
        for (int d = 0; d < 5; ++d) {
            int hs = hh - dys[d], ws = ww - dxs[d];
            vald[d] = ((unsigned)hs < HH) && ((unsigned)ws < WWD);
            offs[d] = hs * WWD + ws;
        }
    }

    // B staging mapping
    const int bu = tid & 7;           // 16B unit within 128B row chunk
    const int bn = tid >> 3;          // row base (32 rows/pass)
    const uint32_t sB_u32 = smem_u32(sB);

    float vstage[16];                 // staged A values (8 channel-pairs)

    auto ldg_A = [&](int chunk) {
        const int c0 = chunk * KCH;
        #pragma unroll
        for (int it = 0; it < 8; ++it) {
            const int ch0 = c0 + 2 * (c2 * 8 + it);
            const int d0  = ch_dir(ch0);
            const int d1  = ch_dir(ch0 + 1);
            vstage[2*it]   = vald[d0] ? __ldg(xb + (size_t)ch0       * HWSZ + offs[d0]) : 0.0f;
            vstage[2*it+1] = vald[d1] ? __ldg(xb + (size_t)(ch0 + 1) * HWSZ + offs[d1]) : 0.0f;
        }
    };

    auto sts_A = [&](int buf) {
        uint32_t* Ab = sA + buf * A_BUF_W;
        #pragma unroll
        for (int it = 0; it < 8; ++it) {
            const int pi = c2 * 8 + it;
            __half2 h = __floats2half2_rn(vstage[2*it], vstage[2*it+1]);
            Ab[pxl * 36 + pi] = *reinterpret_cast<uint32_t*>(&h);
        }
    };

    auto cp_B = [&](int chunk, int buf) {
        const int c0 = chunk * KCH;
        #pragma unroll
        for (int itn = 0; itn < 8; ++itn) {
            const int n = bn + 32 * itn;
            const uint32_t dst = sB_u32 + (uint32_t)(buf * 256 + n) * 144 + bu * 16;
            const __half* src = g_w + (size_t)n * CIN + c0 + bu * 8;
            CP_ASYNC16(dst, src);
        }
    };

    float d[2][8][4];
    #pragma unroll
    for (int mi = 0; mi < 2; ++mi)
        #pragma unroll
        for (int f = 0; f < 8; ++f)
            #pragma unroll
            for (int e = 0; e < 4; ++e) d[mi][f][e] = 0.0f;

    // ---- prologue -----------------------------------------------------------
    ldg_A(0);
    cp_B(0, 0);
    CP_COMMIT();
    sts_A(0);

    // ---- main loop ----------------------------------------------------------
    #pragma unroll 1
    for (int i = 0; i < NCHUNK; ++i) {
        const int buf = i & 1;
        CP_WAIT0();
        __syncthreads();                       // A(i), B(i) visible

        if (i < NCHUNK - 1) {
            ldg_A(i + 1);                      // long-latency loads issue early
            cp_B(i + 1, buf ^ 1);
            CP_COMMIT();
        }

        {
            const uint32_t* Ab = sA + buf * A_BUF_W;
            const uint32_t* Bb = sB + buf * 256 * 36;
            #pragma unroll
            for (int kk = 0; kk < 4; ++kk) {
                uint32_t b0[8], b1[8];
                #pragma unroll
                for (int f = 0; f < 8; ++f) {
                    const int n = warp_n + f * 8 + gr;
                    b0[f] = Bb[n * 36 + kk * 8 + lq];
                    b1[f] = Bb[n * 36 + kk * 8 + lq + 4];
                }
                uint32_t a[2][4];
                #pragma unroll
                for (int mi = 0; mi < 2; ++mi) {
                    const int r = warp_px + mi * 16;
                    a[mi][0] = Ab[(r + gr)     * 36 + kk * 8 + lq];
                    a[mi][1] = Ab[(r + gr + 8) * 36 + kk * 8 + lq];
                    a[mi][2] = Ab[(r + gr)     * 36 + kk * 8 + lq + 4];
                    a[mi][3] = Ab[(r + gr + 8) * 36 + kk * 8 + lq + 4];
                }
                #pragma unroll
                for (int mi = 0; mi < 2; ++mi)
                    #pragma unroll
                    for (int f = 0; f < 8; ++f)
                        MMA16816(d[mi][f], a[mi][0], a[mi][1], a[mi][2], a[mi][3],
                                 b0[f], b1[f]);
            }
        }

        if (i < NCHUNK - 1) sts_A(buf ^ 1);    // published by next-iter barrier
    }

    // ---- epilogue: bias + relu + store -------------------------------------
    #pragma unroll
    for (int mi = 0; mi < 2; ++mi) {
        #pragma unroll
        for (int h2 = 0; h2 < 2; ++h2) {
            const int pxe = warp_px + mi * 16 + gr + 8 * h2;
            const int Pe  = blockIdx.x * CTA_M + pxe;
            const int be  = Pe / HWSZ;
            const int hwe = Pe - be * HWSZ;
            float* ob = out + (size_t)be * COUT * HWSZ + hwe;
            #pragma unroll
            for (int f = 0; f < 8; ++f) {
                const int o = warp_n + f * 8 + lq * 2;
                const float2 bi = *(const float2*)&sbias[o];
                float v0 = d[mi][f][h2 * 2 + 0] + bi.x;
                float v1 = d[mi][f][h2 * 2 + 1] + bi.y;
                ob[(size_t)o       * HWSZ] = fmaxf(v0, 0.0f);
                ob[(size_t)(o + 1) * HWSZ] = fmaxf(v1, 0.0f);
            }
        }
    }
}

// ============================================================================
extern "C" void kernel_launch(void* const* d_in, const int* in_sizes, int n_in,
                              void* d_out, int out_size) {
    const float* x     = (const float*)d_in[0];
    const float* pw    = (const float*)d_in[1];
    const float* gamma = (const float*)d_in[2];
    const float* beta  = (const float*)d_in[3];
    const float* rmean = (const float*)d_in[4];
    const float* rvar  = (const float*)d_in[5];
    float* out = (float*)d_out;

    static bool attr_set = false;
    if (!attr_set) {
        cudaFuncSetAttribute(shiftconv_kernel,
                             cudaFuncAttributeMaxDynamicSharedMemorySize, SMEM_BYTES);
        attr_set = true;
    }

    prep_kernel<<<COUT, 64>>>(pw, gamma, beta, rmean, rvar);
    shiftconv_kernel<<<GRID, 256, SMEM_BYTES>>>(x, out);
}